// round 12
// baseline (speedup 1.0000x reference)
#include <cuda_runtime.h>
#include <cuda_fp16.h>
#include <math.h>

#define B_   8
#define C_   64
#define H_   384
#define W_   384
#define TILE 64
#define SHW  68          // sh row stride in HALVES: 136B (=8 mod 16: conflict-free)
#define NTH  256

// Per-batch precomputed filter state (params are device-resident only)
__device__ float d_gw[B_][12];
__device__ int   d_kk[B_];

__global__ void prep_kernel(const float* __restrict__ params) {
    int b = threadIdx.x;
    if (b >= B_) return;
    float p0 = params[2 * b + 0];
    float p1 = params[2 * b + 1];
    float ki = truncf(p0);
    float s0 = 1.0f / (1.0f + expf(-ki));
    int k = (int)floorf(5.0f + 5.0f * s0);
    k = min(9, max(5, k));
    float s1 = 1.0f / (1.0f + expf(-p1));
    float sigma = 0.5f + 4.5f * s1;
    float inv2s2 = 1.0f / (2.0f * sigma * sigma);
    int half = k >> 1;
    float e[9];
    float sum = 0.0f;
    for (int u = 0; u < k; u++) {
        float c = (float)(u - half);
        e[u] = expf(-c * c * inv2s2);
        sum += e[u];
    }
    float inv = 1.0f / sum;
    for (int u = 0; u < 12; u++)
        d_gw[b][u] = (u < k) ? e[u] * inv : 0.0f;
    d_kk[b] = k;
}

template <int K>
__device__ __forceinline__ void blur_body(const float* __restrict__ xp,
                                          float* __restrict__ op,
                                          __half* sh, float* sc64, float* t64,
                                          const float* __restrict__ gw,
                                          int ti0, int tj0) {
    const int tid = threadIdx.x;
    constexpr int PAD  = K / 2;
    constexpr int OFF  = 4 - PAD;            // 0..2
    constexpr bool EVEN = (K % 2 == 0);
    constexpr int NB   = K + OFF - 1;        // neighbor floats actually needed (<=8)

    float g[K];
#pragma unroll
    for (int u = 0; u < K; u++) g[u] = gw[u];

    // ---- Phase 1: horizontal conv from gmem, shuffle-shared windows ----
    // 72 rows x 8 col-lanes = 576 tasks (warp-aligned). Lane c owns sx-cols
    // [8c, 8c+8); right part of its window comes from lane c+1 via shfl.
    // Result stored as fp16 (fp32 accumulate, RN round).
    for (int t = tid; t < 576; t += NTH) {
        int r = t >> 3;                       // 0..71
        int c = t & 7;                        // 0..7
        int q0 = c * 8;                       // owned sx-col base
        int gi = ti0 - 4 + r;
        bool rowok = (gi >= 0) && (gi < H_);
        const float* rowp = xp + (size_t)gi * W_;

        float o8[8];
#pragma unroll
        for (int i = 0; i < 2; i++) {
            int gj = tj0 - 4 + q0 + 4 * i;    // mult of 4: float4 all-in/all-out
            float4 v = make_float4(0.f, 0.f, 0.f, 0.f);
            if (rowok && gj >= 0 && gj < W_)
                v = *reinterpret_cast<const float4*>(rowp + gj);
            o8[4*i] = v.x; o8[4*i+1] = v.y; o8[4*i+2] = v.z; o8[4*i+3] = v.w;
        }
        float nb[8];
#pragma unroll
        for (int i = 0; i < NB; i++)
            nb[i] = __shfl_down_sync(0xffffffffu, o8[i], 1);
#pragma unroll
        for (int i = NB; i < 8; i++) nb[i] = 0.f;
        if (c == 7) {
            // window cols 64..71 (gj = tj0+60, tj0+64)
#pragma unroll
            for (int i = 0; i < 2; i++) {
                int gj = tj0 + 60 + 4 * i;
                float4 v = make_float4(0.f, 0.f, 0.f, 0.f);
                if (rowok && gj < W_)
                    v = *reinterpret_cast<const float4*>(rowp + gj);
                nb[4*i] = v.x; nb[4*i+1] = v.y; nb[4*i+2] = v.z; nb[4*i+3] = v.w;
            }
        }
        float a[16] = {o8[0], o8[1], o8[2], o8[3], o8[4], o8[5], o8[6], o8[7],
                       nb[0], nb[1], nb[2], nb[3], nb[4], nb[5], nb[6], nb[7]};
        char* dstb = reinterpret_cast<char*>(sh) + r * (SHW * 2) + q0 * 2;
#pragma unroll
        for (int i = 0; i < 2; i++) {
            float acc0 = 0.f, acc1 = 0.f, acc2 = 0.f, acc3 = 0.f;
#pragma unroll
            for (int v = 0; v < K; v++) {
                acc0 = fmaf(g[v], a[4*i + 0 + OFF + v], acc0);
                acc1 = fmaf(g[v], a[4*i + 1 + OFF + v], acc1);
                acc2 = fmaf(g[v], a[4*i + 2 + OFF + v], acc2);
                acc3 = fmaf(g[v], a[4*i + 3 + OFF + v], acc3);
            }
            __half2 h0 = __floats2half2_rn(acc0, acc1);
            __half2 h1 = __floats2half2_rn(acc2, acc3);
            uint2 u;
            u.x = *reinterpret_cast<unsigned*>(&h0);
            u.y = *reinterpret_cast<unsigned*>(&h1);
            *reinterpret_cast<uint2*>(dstb + 8 * i) = u;
        }
    }
    // extra column q=64 (only needed by even-K blend) kept in fp32
    if (EVEN && tid < 72) {
        int r  = tid;
        int gi = ti0 - 4 + r;
        bool rowok = (gi >= 0) && (gi < H_);
        const float* rowp = xp + (size_t)gi * W_;
        float a[8];
#pragma unroll
        for (int i = 0; i < 2; i++) {
            int gj = tj0 + 60 + 4 * i;
            float4 v = make_float4(0.f, 0.f, 0.f, 0.f);
            if (rowok && gj < W_)
                v = *reinterpret_cast<const float4*>(rowp + gj);
            a[4*i] = v.x; a[4*i+1] = v.y; a[4*i+2] = v.z; a[4*i+3] = v.w;
        }
        float acc = 0.f;
#pragma unroll
        for (int v = 0; v < K; v++) acc = fmaf(g[v], a[OFF + v], acc);
        sc64[r] = acc;
    }
    __syncthreads();

    // ---- Phase 2: vertical conv, 8-row half2 slide, direct epilogue ----
    const int rg = tid >> 5;                  // 0..7
    const int cg = tid & 31;                  // 0..31
    const int p0 = rg * 8;
    const int j0 = cg * 2;
    const char* shb = reinterpret_cast<const char*>(sh);

    if (!EVEN) {
        float2 acc[8];
#pragma unroll
        for (int m = 0; m < 8; m++) acc[m] = make_float2(0.f, 0.f);
#pragma unroll
        for (int r = 0; r < K + 7; r++) {
            __half2 wh = *reinterpret_cast<const __half2*>(
                shb + (p0 + OFF + r) * (SHW * 2) + j0 * 2);
            float2 w = __half22float2(wh);
#pragma unroll
            for (int m = 0; m < 8; m++) {
                if (r >= m && r - m < K) {
                    float gv = g[r - m];
                    acc[m].x = fmaf(gv, w.x, acc[m].x);
                    acc[m].y = fmaf(gv, w.y, acc[m].y);
                }
            }
        }
#pragma unroll
        for (int m = 0; m < 8; m++)
            *reinterpret_cast<float2*>(op + (size_t)(ti0 + p0 + m) * W_ + tj0 + j0) = acc[m];
    } else {
        // One-shot side pass: t64[p] = vertical conv of col 64 (fp32), p=0..64.
        if (tid < 65) {
            float e = 0.f;
#pragma unroll
            for (int u = 0; u < K; u++)
                e = fmaf(g[u], sc64[tid + OFF + u], e);
            t64[tid] = e;
        }

        // 9-row vertical conv in registers
        float2 acc[9];
#pragma unroll
        for (int m = 0; m < 9; m++) acc[m] = make_float2(0.f, 0.f);
#pragma unroll
        for (int r = 0; r < K + 8; r++) {
            __half2 wh = *reinterpret_cast<const __half2*>(
                shb + (p0 + OFF + r) * (SHW * 2) + j0 * 2);
            float2 w = __half22float2(wh);
#pragma unroll
            for (int m = 0; m < 9; m++) {
                if (r >= m && r - m < K) {
                    float gv = g[r - m];
                    acc[m].x = fmaf(gv, w.x, acc[m].x);
                    acc[m].y = fmaf(gv, w.y, acc[m].y);
                }
            }
        }
        __syncthreads();   // t64 visible (uniform: EVEN is compile-time)

        const bool last = (cg == 31);
        const float inv384 = 1.0f / 384.0f;
        float fj0 = ((float)(tj0 + j0 + 0) + 0.5f) * inv384;
        float fj1 = ((float)(tj0 + j0 + 1) + 0.5f) * inv384;
        float rn_next;
        {
            float v = __shfl_down_sync(0xffffffffu, acc[0].x, 1);
            rn_next = last ? t64[p0] : v;
        }
#pragma unroll
        for (int m = 0; m < 8; m++) {
            float rn_m = rn_next;
            float v = __shfl_down_sync(0xffffffffu, acc[m + 1].x, 1);
            rn_next = last ? t64[p0 + m + 1] : v;

            float fi = ((float)(ti0 + p0 + m) + 0.5f) * inv384;
            float top0 = fmaf(fj0, acc[m].y   - acc[m].x,   acc[m].x);
            float bot0 = fmaf(fj0, acc[m+1].y - acc[m+1].x, acc[m+1].x);
            float top1 = fmaf(fj1, rn_m       - acc[m].y,   acc[m].y);
            float bot1 = fmaf(fj1, rn_next    - acc[m+1].y, acc[m+1].y);
            float2 o;
            o.x = fmaf(fi, bot0 - top0, top0);
            o.y = fmaf(fi, bot1 - top1, top1);
            *reinterpret_cast<float2*>(op + (size_t)(ti0 + p0 + m) * W_ + tj0 + j0) = o;
        }
    }
}

__global__ __launch_bounds__(NTH, 7)
void blur_kernel(const float* __restrict__ x, float* __restrict__ out) {
    __shared__ __half sh[72 * SHW];           // fp16 h-conv tile (cols 0..63)
    __shared__ float  sc64[72];               // fp32 h-conv col 64
    __shared__ float  t64[65];                // fp32 v-conv of col 64
    int bc = blockIdx.z;
    int b = bc >> 6;
    int c = bc & 63;
    int ti0 = blockIdx.y * TILE;
    int tj0 = blockIdx.x * TILE;
    const float* xp = x + (size_t)(b * C_ + c) * (H_ * W_);
    float* op = out + (size_t)(b * C_ + c) * (H_ * W_);
    const float* gw = d_gw[b];
    switch (d_kk[b]) {
        case 5: blur_body<5>(xp, op, sh, sc64, t64, gw, ti0, tj0); break;
        case 6: blur_body<6>(xp, op, sh, sc64, t64, gw, ti0, tj0); break;
        case 7: blur_body<7>(xp, op, sh, sc64, t64, gw, ti0, tj0); break;
        case 8: blur_body<8>(xp, op, sh, sc64, t64, gw, ti0, tj0); break;
        default: blur_body<9>(xp, op, sh, sc64, t64, gw, ti0, tj0); break;
    }
}

extern "C" void kernel_launch(void* const* d_in, const int* in_sizes, int n_in,
                              void* d_out, int out_size) {
    const float* x      = (const float*)d_in[0];
    const float* params = (const float*)d_in[1];
    if (n_in >= 2 && in_sizes[0] < in_sizes[1]) {
        const float* t = x; x = params; params = t;
    }
    float* out = (float*)d_out;

    prep_kernel<<<1, 32>>>(params);
    dim3 grid(W_ / TILE, H_ / TILE, B_ * C_);
    blur_kernel<<<grid, NTH>>>(x, out);
}

// round 13
// speedup vs baseline: 1.0988x; 1.0988x over previous
#include <cuda_runtime.h>
#include <cuda_fp16.h>
#include <math.h>

#define B_   8
#define C_   64
#define H_   384
#define W_   384
#define TW   64          // tile width
#define TH   128         // tile height
#define ROWS 136         // TH + 8 halo rows
#define SHW  68          // sh row stride in HALVES: 136B
#define NTH  256

// Per-batch precomputed filter state (params are device-resident only)
__device__ float d_gw[B_][12];
__device__ int   d_kk[B_];

__global__ void prep_kernel(const float* __restrict__ params) {
    int b = threadIdx.x;
    if (b >= B_) return;
    float p0 = params[2 * b + 0];
    float p1 = params[2 * b + 1];
    float ki = truncf(p0);
    float s0 = 1.0f / (1.0f + expf(-ki));
    int k = (int)floorf(5.0f + 5.0f * s0);
    k = min(9, max(5, k));
    float s1 = 1.0f / (1.0f + expf(-p1));
    float sigma = 0.5f + 4.5f * s1;
    float inv2s2 = 1.0f / (2.0f * sigma * sigma);
    int half = k >> 1;
    float e[9];
    float sum = 0.0f;
    for (int u = 0; u < k; u++) {
        float c = (float)(u - half);
        e[u] = expf(-c * c * inv2s2);
        sum += e[u];
    }
    float inv = 1.0f / sum;
    for (int u = 0; u < 12; u++)
        d_gw[b][u] = (u < k) ? e[u] * inv : 0.0f;
    d_kk[b] = k;
}

template <int K>
__device__ __forceinline__ void blur_body(const float* __restrict__ xp,
                                          float* __restrict__ op,
                                          __half* sh, float* sc64, float* t64,
                                          const float* __restrict__ gw,
                                          int ti0, int tj0) {
    const int tid = threadIdx.x;
    constexpr int PAD  = K / 2;
    constexpr int OFF  = 4 - PAD;            // 0..2
    constexpr bool EVEN = (K % 2 == 0);
    constexpr int NB   = K + OFF - 1;        // neighbor floats needed (<=8)

    float g[K];
#pragma unroll
    for (int u = 0; u < K; u++) g[u] = gw[u];

    // ---- Phase 1: horizontal conv from gmem, shuffle-shared windows ----
    // ROWS x 8 col-lanes = 1088 tasks (full-warp tail: 1088-1024=64=2 warps).
    for (int t = tid; t < ROWS * 8; t += NTH) {
        int r = t >> 3;                       // 0..135
        int c = t & 7;                        // 0..7
        int q0 = c * 8;                       // owned sx-col base
        int gi = ti0 - 4 + r;
        bool rowok = (gi >= 0) && (gi < H_);
        const float* rowp = xp + (size_t)gi * W_;

        float o8[8];
#pragma unroll
        for (int i = 0; i < 2; i++) {
            int gj = tj0 - 4 + q0 + 4 * i;    // mult of 4: float4 all-in/all-out
            float4 v = make_float4(0.f, 0.f, 0.f, 0.f);
            if (rowok && gj >= 0 && gj < W_)
                v = *reinterpret_cast<const float4*>(rowp + gj);
            o8[4*i] = v.x; o8[4*i+1] = v.y; o8[4*i+2] = v.z; o8[4*i+3] = v.w;
        }
        float nb[8];
#pragma unroll
        for (int i = 0; i < NB; i++)
            nb[i] = __shfl_down_sync(0xffffffffu, o8[i], 1);
#pragma unroll
        for (int i = NB; i < 8; i++) nb[i] = 0.f;
        if (c == 7) {
#pragma unroll
            for (int i = 0; i < 2; i++) {
                int gj = tj0 + 60 + 4 * i;
                float4 v = make_float4(0.f, 0.f, 0.f, 0.f);
                if (rowok && gj < W_)
                    v = *reinterpret_cast<const float4*>(rowp + gj);
                nb[4*i] = v.x; nb[4*i+1] = v.y; nb[4*i+2] = v.z; nb[4*i+3] = v.w;
            }
        }
        float a[16] = {o8[0], o8[1], o8[2], o8[3], o8[4], o8[5], o8[6], o8[7],
                       nb[0], nb[1], nb[2], nb[3], nb[4], nb[5], nb[6], nb[7]};
        char* dstb = reinterpret_cast<char*>(sh) + r * (SHW * 2) + q0 * 2;
#pragma unroll
        for (int i = 0; i < 2; i++) {
            float acc0 = 0.f, acc1 = 0.f, acc2 = 0.f, acc3 = 0.f;
#pragma unroll
            for (int v = 0; v < K; v++) {
                acc0 = fmaf(g[v], a[4*i + 0 + OFF + v], acc0);
                acc1 = fmaf(g[v], a[4*i + 1 + OFF + v], acc1);
                acc2 = fmaf(g[v], a[4*i + 2 + OFF + v], acc2);
                acc3 = fmaf(g[v], a[4*i + 3 + OFF + v], acc3);
            }
            __half2 h0 = __floats2half2_rn(acc0, acc1);
            __half2 h1 = __floats2half2_rn(acc2, acc3);
            uint2 u;
            u.x = *reinterpret_cast<unsigned*>(&h0);
            u.y = *reinterpret_cast<unsigned*>(&h1);
            *reinterpret_cast<uint2*>(dstb + 8 * i) = u;
        }
    }
    // extra column q=64 (even-K blend only), fp32, rows 0..135
    if (EVEN && tid < ROWS) {
        int r  = tid;
        int gi = ti0 - 4 + r;
        bool rowok = (gi >= 0) && (gi < H_);
        const float* rowp = xp + (size_t)gi * W_;
        float a[8];
#pragma unroll
        for (int i = 0; i < 2; i++) {
            int gj = tj0 + 60 + 4 * i;
            float4 v = make_float4(0.f, 0.f, 0.f, 0.f);
            if (rowok && gj < W_)
                v = *reinterpret_cast<const float4*>(rowp + gj);
            a[4*i] = v.x; a[4*i+1] = v.y; a[4*i+2] = v.z; a[4*i+3] = v.w;
        }
        float acc = 0.f;
#pragma unroll
        for (int v = 0; v < K; v++) acc = fmaf(g[v], a[OFF + v], acc);
        sc64[r] = acc;
    }
    __syncthreads();

    // ---- Phase 2: vertical conv, 16-row streaming ring, direct epilogue ----
    const int rg = tid >> 5;                  // 0..7
    const int cg = tid & 31;                  // 0..31
    const int p0 = rg * 16;
    const int j0 = cg * 2;
    const char* shb = reinterpret_cast<const char*>(sh);
    const char* src0 = shb + (p0 + OFF) * (SHW * 2) + j0 * 2;

    if (!EVEN) {
        float2 acc[K];
#pragma unroll
        for (int s = 0; s < K; s++) acc[s] = make_float2(0.f, 0.f);
#pragma unroll
        for (int r = 0; r < K + 15; r++) {
            __half2 wh = *reinterpret_cast<const __half2*>(src0 + r * (SHW * 2));
            float2 w = __half22float2(wh);
#pragma unroll
            for (int o = 0; o < 16; o++) {
                if (o <= r && r - o < K) {
                    float gv = g[r - o];
                    acc[o % K].x = fmaf(gv, w.x, acc[o % K].x);
                    acc[o % K].y = fmaf(gv, w.y, acc[o % K].y);
                }
            }
            if (r >= K - 1) {
                constexpr int dummy = 0; (void)dummy;
                int o = r - (K - 1);          // completed output row (0..15)
                if (o < 16) {
                    *reinterpret_cast<float2*>(
                        op + (size_t)(ti0 + p0 + o) * W_ + tj0 + j0) = acc[o % K];
                    acc[o % K] = make_float2(0.f, 0.f);
                }
            }
        }
    } else {
        // side pass: t64[p] = vertical conv of col 64 (fp32), p = 0..128
        if (tid < TH + 1) {
            float e = 0.f;
#pragma unroll
            for (int u = 0; u < K; u++)
                e = fmaf(g[u], sc64[tid + OFF + u], e);
            t64[tid] = e;
        }
        __syncthreads();   // t64 visible (uniform: EVEN is compile-time)

        const bool last = (cg == 31);
        const float inv384 = 1.0f / 384.0f;
        float fj0 = ((float)(tj0 + j0 + 0) + 0.5f) * inv384;
        float fj1 = ((float)(tj0 + j0 + 1) + 0.5f) * inv384;

        float2 acc[K];
#pragma unroll
        for (int s = 0; s < K; s++) acc[s] = make_float2(0.f, 0.f);
        float2 prev = make_float2(0.f, 0.f);
        float  rn_prev = 0.f;
#pragma unroll
        for (int r = 0; r < K + 16; r++) {
            __half2 wh = *reinterpret_cast<const __half2*>(src0 + r * (SHW * 2));
            float2 w = __half22float2(wh);
#pragma unroll
            for (int o = 0; o <= 16; o++) {
                if (o <= r && r - o < K) {
                    float gv = g[r - o];
                    acc[o % K].x = fmaf(gv, w.x, acc[o % K].x);
                    acc[o % K].y = fmaf(gv, w.y, acc[o % K].y);
                }
            }
            if (r >= K - 1) {
                int o = r - (K - 1);          // completed t-row (0..16)
                float2 cur = acc[o % K];
                acc[o % K] = make_float2(0.f, 0.f);
                float v = __shfl_down_sync(0xffffffffu, cur.x, 1);
                float rn_cur = last ? t64[p0 + o] : v;
                if (o >= 1) {
                    int orow = o - 1;         // output row p0+orow
                    float fi = ((float)(ti0 + p0 + orow) + 0.5f) * inv384;
                    float top0 = fmaf(fj0, prev.y   - prev.x, prev.x);
                    float bot0 = fmaf(fj0, cur.y    - cur.x,  cur.x);
                    float top1 = fmaf(fj1, rn_prev  - prev.y, prev.y);
                    float bot1 = fmaf(fj1, rn_cur   - cur.y,  cur.y);
                    float2 out2;
                    out2.x = fmaf(fi, bot0 - top0, top0);
                    out2.y = fmaf(fi, bot1 - top1, top1);
                    *reinterpret_cast<float2*>(
                        op + (size_t)(ti0 + p0 + orow) * W_ + tj0 + j0) = out2;
                }
                prev = cur;
                rn_prev = rn_cur;
            }
        }
    }
}

__global__ __launch_bounds__(NTH, 7)
void blur_kernel(const float* __restrict__ x, float* __restrict__ out) {
    __shared__ __half sh[ROWS * SHW];         // fp16 h-conv tile (cols 0..63)
    __shared__ float  sc64[ROWS];             // fp32 h-conv col 64
    __shared__ float  t64[TH + 1];            // fp32 v-conv of col 64
    int bc = blockIdx.z;
    int b = bc >> 6;
    int c = bc & 63;
    int ti0 = blockIdx.y * TH;
    int tj0 = blockIdx.x * TW;
    const float* xp = x + (size_t)(b * C_ + c) * (H_ * W_);
    float* op = out + (size_t)(b * C_ + c) * (H_ * W_);
    const float* gw = d_gw[b];
    switch (d_kk[b]) {
        case 5: blur_body<5>(xp, op, sh, sc64, t64, gw, ti0, tj0); break;
        case 6: blur_body<6>(xp, op, sh, sc64, t64, gw, ti0, tj0); break;
        case 7: blur_body<7>(xp, op, sh, sc64, t64, gw, ti0, tj0); break;
        case 8: blur_body<8>(xp, op, sh, sc64, t64, gw, ti0, tj0); break;
        default: blur_body<9>(xp, op, sh, sc64, t64, gw, ti0, tj0); break;
    }
}

extern "C" void kernel_launch(void* const* d_in, const int* in_sizes, int n_in,
                              void* d_out, int out_size) {
    const float* x      = (const float*)d_in[0];
    const float* params = (const float*)d_in[1];
    if (n_in >= 2 && in_sizes[0] < in_sizes[1]) {
        const float* t = x; x = params; params = t;
    }
    float* out = (float*)d_out;

    prep_kernel<<<1, 32>>>(params);
    dim3 grid(W_ / TW, H_ / TH, B_ * C_);
    blur_kernel<<<grid, NTH>>>(x, out);
}

// round 14
// speedup vs baseline: 1.0997x; 1.0009x over previous
#include <cuda_runtime.h>
#include <cuda_fp16.h>
#include <math.h>

#define B_   8
#define C_   64
#define H_   384
#define W_   384
#define TW   64          // tile width
#define TH   128         // tile height
#define ROWS 136         // TH + 8 halo rows
#define SHW  68          // sh row stride in HALVES: 136B
#define NTH  256

// Per-batch precomputed filter state (params are device-resident only)
__device__ float d_gw[B_][12];
__device__ int   d_kk[B_];

__global__ void prep_kernel(const float* __restrict__ params) {
    int b = threadIdx.x;
    if (b >= B_) return;
    float p0 = params[2 * b + 0];
    float p1 = params[2 * b + 1];
    float ki = truncf(p0);
    float s0 = 1.0f / (1.0f + expf(-ki));
    int k = (int)floorf(5.0f + 5.0f * s0);
    k = min(9, max(5, k));
    float s1 = 1.0f / (1.0f + expf(-p1));
    float sigma = 0.5f + 4.5f * s1;
    float inv2s2 = 1.0f / (2.0f * sigma * sigma);
    int half = k >> 1;
    float e[9];
    float sum = 0.0f;
    for (int u = 0; u < k; u++) {
        float c = (float)(u - half);
        e[u] = expf(-c * c * inv2s2);
        sum += e[u];
    }
    float inv = 1.0f / sum;
    for (int u = 0; u < 12; u++)
        d_gw[b][u] = (u < k) ? e[u] * inv : 0.0f;
    d_kk[b] = k;
}

template <int K>
__device__ __forceinline__ void blur_body(const float* __restrict__ xp,
                                          float* __restrict__ op,
                                          __half* sh, float* sc64, float* t64,
                                          const float* __restrict__ gw,
                                          int ti0, int tj0) {
    const int tid = threadIdx.x;
    constexpr int PAD  = K / 2;
    constexpr int OFF  = 4 - PAD;            // 0..2
    constexpr bool EVEN = (K % 2 == 0);
    constexpr int NB   = K + OFF - 1;        // neighbor floats needed (<=8)

    float g[K];
#pragma unroll
    for (int u = 0; u < K; u++) g[u] = gw[u];

    // ---- Phase 1: horizontal conv from gmem, shuffle-shared windows ----
    // ROWS x 8 col-lanes = 1088 tasks (full-warp tail: 1088-1024=64=2 warps).
    for (int t = tid; t < ROWS * 8; t += NTH) {
        int r = t >> 3;                       // 0..135
        int c = t & 7;                        // 0..7
        int q0 = c * 8;                       // owned sx-col base
        int gi = ti0 - 4 + r;
        bool rowok = (gi >= 0) && (gi < H_);
        const float* rowp = xp + (size_t)gi * W_;

        float o8[8];
#pragma unroll
        for (int i = 0; i < 2; i++) {
            int gj = tj0 - 4 + q0 + 4 * i;    // mult of 4: float4 all-in/all-out
            float4 v = make_float4(0.f, 0.f, 0.f, 0.f);
            if (rowok && gj >= 0 && gj < W_)
                v = *reinterpret_cast<const float4*>(rowp + gj);
            o8[4*i] = v.x; o8[4*i+1] = v.y; o8[4*i+2] = v.z; o8[4*i+3] = v.w;
        }
        float nb[8];
#pragma unroll
        for (int i = 0; i < NB; i++)
            nb[i] = __shfl_down_sync(0xffffffffu, o8[i], 1);
#pragma unroll
        for (int i = NB; i < 8; i++) nb[i] = 0.f;
        if (c == 7) {
#pragma unroll
            for (int i = 0; i < 2; i++) {
                int gj = tj0 + 60 + 4 * i;
                float4 v = make_float4(0.f, 0.f, 0.f, 0.f);
                if (rowok && gj < W_)
                    v = *reinterpret_cast<const float4*>(rowp + gj);
                nb[4*i] = v.x; nb[4*i+1] = v.y; nb[4*i+2] = v.z; nb[4*i+3] = v.w;
            }
        }
        float a[16] = {o8[0], o8[1], o8[2], o8[3], o8[4], o8[5], o8[6], o8[7],
                       nb[0], nb[1], nb[2], nb[3], nb[4], nb[5], nb[6], nb[7]};
        char* dstb = reinterpret_cast<char*>(sh) + r * (SHW * 2) + q0 * 2;
#pragma unroll
        for (int i = 0; i < 2; i++) {
            float acc0 = 0.f, acc1 = 0.f, acc2 = 0.f, acc3 = 0.f;
#pragma unroll
            for (int v = 0; v < K; v++) {
                acc0 = fmaf(g[v], a[4*i + 0 + OFF + v], acc0);
                acc1 = fmaf(g[v], a[4*i + 1 + OFF + v], acc1);
                acc2 = fmaf(g[v], a[4*i + 2 + OFF + v], acc2);
                acc3 = fmaf(g[v], a[4*i + 3 + OFF + v], acc3);
            }
            __half2 h0 = __floats2half2_rn(acc0, acc1);
            __half2 h1 = __floats2half2_rn(acc2, acc3);
            uint2 u;
            u.x = *reinterpret_cast<unsigned*>(&h0);
            u.y = *reinterpret_cast<unsigned*>(&h1);
            *reinterpret_cast<uint2*>(dstb + 8 * i) = u;
        }
    }
    // extra column q=64 (even-K blend only), fp32, rows 0..135
    if (EVEN && tid < ROWS) {
        int r  = tid;
        int gi = ti0 - 4 + r;
        bool rowok = (gi >= 0) && (gi < H_);
        const float* rowp = xp + (size_t)gi * W_;
        float a[8];
#pragma unroll
        for (int i = 0; i < 2; i++) {
            int gj = tj0 + 60 + 4 * i;
            float4 v = make_float4(0.f, 0.f, 0.f, 0.f);
            if (rowok && gj < W_)
                v = *reinterpret_cast<const float4*>(rowp + gj);
            a[4*i] = v.x; a[4*i+1] = v.y; a[4*i+2] = v.z; a[4*i+3] = v.w;
        }
        float acc = 0.f;
#pragma unroll
        for (int v = 0; v < K; v++) acc = fmaf(g[v], a[OFF + v], acc);
        sc64[r] = acc;
    }
    __syncthreads();

    // ---- Phase 2: vertical conv, 16-row streaming ring, direct epilogue ----
    const int rg = tid >> 5;                  // 0..7
    const int cg = tid & 31;                  // 0..31
    const int p0 = rg * 16;
    const int j0 = cg * 2;
    const char* shb = reinterpret_cast<const char*>(sh);
    const char* src0 = shb + (p0 + OFF) * (SHW * 2) + j0 * 2;

    if (!EVEN) {
        float2 acc[K];
#pragma unroll
        for (int s = 0; s < K; s++) acc[s] = make_float2(0.f, 0.f);
#pragma unroll
        for (int r = 0; r < K + 15; r++) {
            __half2 wh = *reinterpret_cast<const __half2*>(src0 + r * (SHW * 2));
            float2 w = __half22float2(wh);
#pragma unroll
            for (int o = 0; o < 16; o++) {
                if (o <= r && r - o < K) {
                    float gv = g[r - o];
                    acc[o % K].x = fmaf(gv, w.x, acc[o % K].x);
                    acc[o % K].y = fmaf(gv, w.y, acc[o % K].y);
                }
            }
            if (r >= K - 1) {
                constexpr int dummy = 0; (void)dummy;
                int o = r - (K - 1);          // completed output row (0..15)
                if (o < 16) {
                    *reinterpret_cast<float2*>(
                        op + (size_t)(ti0 + p0 + o) * W_ + tj0 + j0) = acc[o % K];
                    acc[o % K] = make_float2(0.f, 0.f);
                }
            }
        }
    } else {
        // side pass: t64[p] = vertical conv of col 64 (fp32), p = 0..128
        if (tid < TH + 1) {
            float e = 0.f;
#pragma unroll
            for (int u = 0; u < K; u++)
                e = fmaf(g[u], sc64[tid + OFF + u], e);
            t64[tid] = e;
        }
        __syncthreads();   // t64 visible (uniform: EVEN is compile-time)

        const bool last = (cg == 31);
        const float inv384 = 1.0f / 384.0f;
        float fj0 = ((float)(tj0 + j0 + 0) + 0.5f) * inv384;
        float fj1 = ((float)(tj0 + j0 + 1) + 0.5f) * inv384;

        float2 acc[K];
#pragma unroll
        for (int s = 0; s < K; s++) acc[s] = make_float2(0.f, 0.f);
        float2 prev = make_float2(0.f, 0.f);
        float  rn_prev = 0.f;
#pragma unroll
        for (int r = 0; r < K + 16; r++) {
            __half2 wh = *reinterpret_cast<const __half2*>(src0 + r * (SHW * 2));
            float2 w = __half22float2(wh);
#pragma unroll
            for (int o = 0; o <= 16; o++) {
                if (o <= r && r - o < K) {
                    float gv = g[r - o];
                    acc[o % K].x = fmaf(gv, w.x, acc[o % K].x);
                    acc[o % K].y = fmaf(gv, w.y, acc[o % K].y);
                }
            }
            if (r >= K - 1) {
                int o = r - (K - 1);          // completed t-row (0..16)
                float2 cur = acc[o % K];
                acc[o % K] = make_float2(0.f, 0.f);
                float v = __shfl_down_sync(0xffffffffu, cur.x, 1);
                float rn_cur = last ? t64[p0 + o] : v;
                if (o >= 1) {
                    int orow = o - 1;         // output row p0+orow
                    float fi = ((float)(ti0 + p0 + orow) + 0.5f) * inv384;
                    float top0 = fmaf(fj0, prev.y   - prev.x, prev.x);
                    float bot0 = fmaf(fj0, cur.y    - cur.x,  cur.x);
                    float top1 = fmaf(fj1, rn_prev  - prev.y, prev.y);
                    float bot1 = fmaf(fj1, rn_cur   - cur.y,  cur.y);
                    float2 out2;
                    out2.x = fmaf(fi, bot0 - top0, top0);
                    out2.y = fmaf(fi, bot1 - top1, top1);
                    *reinterpret_cast<float2*>(
                        op + (size_t)(ti0 + p0 + orow) * W_ + tj0 + j0) = out2;
                }
                prev = cur;
                rn_prev = rn_cur;
            }
        }
    }
}

__global__ __launch_bounds__(NTH, 7)
void blur_kernel(const float* __restrict__ x, float* __restrict__ out) {
    __shared__ __half sh[ROWS * SHW];         // fp16 h-conv tile (cols 0..63)
    __shared__ float  sc64[ROWS];             // fp32 h-conv col 64
    __shared__ float  t64[TH + 1];            // fp32 v-conv of col 64
    int bc = blockIdx.z;
    int b = bc >> 6;
    int c = bc & 63;
    int ti0 = blockIdx.y * TH;
    int tj0 = blockIdx.x * TW;
    const float* xp = x + (size_t)(b * C_ + c) * (H_ * W_);
    float* op = out + (size_t)(b * C_ + c) * (H_ * W_);
    const float* gw = d_gw[b];
    switch (d_kk[b]) {
        case 5: blur_body<5>(xp, op, sh, sc64, t64, gw, ti0, tj0); break;
        case 6: blur_body<6>(xp, op, sh, sc64, t64, gw, ti0, tj0); break;
        case 7: blur_body<7>(xp, op, sh, sc64, t64, gw, ti0, tj0); break;
        case 8: blur_body<8>(xp, op, sh, sc64, t64, gw, ti0, tj0); break;
        default: blur_body<9>(xp, op, sh, sc64, t64, gw, ti0, tj0); break;
    }
}

extern "C" void kernel_launch(void* const* d_in, const int* in_sizes, int n_in,
                              void* d_out, int out_size) {
    const float* x      = (const float*)d_in[0];
    const float* params = (const float*)d_in[1];
    if (n_in >= 2 && in_sizes[0] < in_sizes[1]) {
        const float* t = x; x = params; params = t;
    }
    float* out = (float*)d_out;

    prep_kernel<<<1, 32>>>(params);
    dim3 grid(W_ / TW, H_ / TH, B_ * C_);
    blur_kernel<<<grid, NTH>>>(x, out);
}